// round 11
// baseline (speedup 1.0000x reference)
#include <cuda_runtime.h>
#include <cuda_fp16.h>
#include <mma.h>
#include <math.h>
#include <stdint.h>

using namespace nvcuda;

#define NN 50000
#define NE 800000
#define F  128
#define MT 128        // rows per MMA block
#define HLD 136       // half leading dim for A/B smem (mult of 8)
#define CLD 132       // float leading dim for C staging
#define SPAD 65       // scores transposed-tile pad

// ---------------- scratch (device globals; no allocation allowed) ----------
__device__ __align__(16) float g_feat[NN * F];
__device__ __align__(16) float g_h1[NN * F];
__device__ __align__(16) float g_h2[NN * F];
__device__ __align__(16) float g_el[NN * 4];
__device__ __align__(16) float g_er[NN * 4];
__device__ __align__(16) float g_ew[NE * 4 + 256];  // per-(edge,head) weights (+pad)
__device__ __align__(16) float g_wl[4 * F];         // W @ al[h]
__device__ __align__(16) float g_wr[4 * F];         // W @ ar[h]
__device__ int g_rowptr[NN + 1];
__device__ unsigned g_elmax_u[3][4];

// ---------------- monotone float<->uint encode for atomicMax ---------------
__device__ __forceinline__ unsigned fenc(float f) {
    unsigned u = __float_as_uint(f);
    return (u & 0x80000000u) ? ~u : (u | 0x80000000u);
}
__device__ __forceinline__ float fdec(unsigned u) {
    return (u & 0x80000000u) ? __uint_as_float(u ^ 0x80000000u)
                             : __uint_as_float(~u);
}

// ---------------- row_ptr (sorted dst, lower_bound) + elmax reset ----------
__global__ void rowptr_kernel(const int* __restrict__ dst) {
    int n = blockIdx.x * blockDim.x + threadIdx.x;
    if (blockIdx.x == 0 && threadIdx.x < 12)
        ((unsigned*)g_elmax_u)[threadIdx.x] = fenc(-3.0e38f);
    if (n > NN) return;
    int lo = 0, hi = NE;
    while (lo < hi) {
        int mid = (lo + hi) >> 1;
        if (dst[mid] < n) lo = mid + 1; else hi = mid;
    }
    g_rowptr[n] = lo;
}

// ---------------- fp16 WMMA GEMM: feat = h @ W  (+ wl/wr on block 0) -------
extern __shared__ __align__(16) char s_raw[];

__global__ __launch_bounds__(256) void mma_kernel(
    const float* __restrict__ hin, const float* __restrict__ W,
    const float* __restrict__ al, const float* __restrict__ ar)
{
    __half* As = reinterpret_cast<__half*>(s_raw);               // [128][HLD]
    __half* Bs = reinterpret_cast<__half*>(s_raw) + MT * HLD;    // [128][HLD]
    float*  Cs = reinterpret_cast<float*>(s_raw);                // [128][CLD]
    const int tid  = threadIdx.x;
    const int base = blockIdx.x * MT;

    // block 0: wl[h]=W@al[h], wr[h]=W@ar[h] (exact fp32)
    if (blockIdx.x == 0) {
        #pragma unroll
        for (int j = 0; j < 4; j++) {
            int o = tid + 256 * j;
            int k = o & 127, hh = o >> 7, h = hh & 3;
            const float* vec = (hh < 4) ? al : ar;
            float s = 0.f;
            #pragma unroll
            for (int d = 0; d < 32; d++)
                s = fmaf(__ldg(&W[k * F + h * 32 + d]), __ldg(&vec[h * 32 + d]), s);
            if (hh < 4) g_wl[h * F + k] = s; else g_wr[h * F + k] = s;
        }
    }

    // ---- fill A (h tile, fp16) and B (W, fp16), coalesced ----
    #pragma unroll
    for (int i = 0; i < 16; i++) {
        int idx = tid + 256 * i;
        int row = idx >> 5, c4 = idx & 31;
        int n = base + row;
        float4 v = (n < NN)
            ? __ldg(reinterpret_cast<const float4*>(&hin[n * F + 4 * c4]))
            : make_float4(0.f, 0.f, 0.f, 0.f);
        __half2 a01 = __floats2half2_rn(v.x, v.y);
        __half2 a23 = __floats2half2_rn(v.z, v.w);
        uint2 pa;
        pa.x = *reinterpret_cast<unsigned*>(&a01);
        pa.y = *reinterpret_cast<unsigned*>(&a23);
        *reinterpret_cast<uint2*>(&As[row * HLD + 4 * c4]) = pa;

        float4 wv = __ldg(reinterpret_cast<const float4*>(&W[idx * 4]));
        __half2 b01 = __floats2half2_rn(wv.x, wv.y);
        __half2 b23 = __floats2half2_rn(wv.z, wv.w);
        uint2 pb;
        pb.x = *reinterpret_cast<unsigned*>(&b01);
        pb.y = *reinterpret_cast<unsigned*>(&b23);
        *reinterpret_cast<uint2*>(&Bs[row * HLD + 4 * c4]) = pb;
    }
    __syncthreads();

    const int w  = tid >> 5;
    const int wr = w & 3;       // rows 32*wr .. +31
    const int wc = w >> 2;      // cols 64*wc .. +63

    wmma::fragment<wmma::accumulator, 16, 16, 16, float> c[2][4];
    #pragma unroll
    for (int i = 0; i < 2; i++)
        #pragma unroll
        for (int j = 0; j < 4; j++) wmma::fill_fragment(c[i][j], 0.f);

    #pragma unroll
    for (int k = 0; k < 8; k++) {
        wmma::fragment<wmma::matrix_a, 16, 16, 16, __half, wmma::row_major> a[2];
        wmma::fragment<wmma::matrix_b, 16, 16, 16, __half, wmma::row_major> b[4];
        #pragma unroll
        for (int i = 0; i < 2; i++)
            wmma::load_matrix_sync(a[i], &As[(32 * wr + 16 * i) * HLD + 16 * k], HLD);
        #pragma unroll
        for (int j = 0; j < 4; j++)
            wmma::load_matrix_sync(b[j], &Bs[16 * k * HLD + 64 * wc + 16 * j], HLD);
        #pragma unroll
        for (int i = 0; i < 2; i++)
            #pragma unroll
            for (int j = 0; j < 4; j++)
                wmma::mma_sync(c[i][j], a[i], b[j], c[i][j]);
    }
    __syncthreads();

    #pragma unroll
    for (int i = 0; i < 2; i++)
        #pragma unroll
        for (int j = 0; j < 4; j++)
            wmma::store_matrix_sync(
                &Cs[(32 * wr + 16 * i) * CLD + 64 * wc + 16 * j],
                c[i][j], CLD, wmma::mem_row_major);
    __syncthreads();

    // ---- coalesced fp32 feat writeout ----
    #pragma unroll
    for (int i = 0; i < 16; i++) {
        int idx = tid + 256 * i;
        int row = idx >> 5, c4 = idx & 31;
        int n = base + row;
        if (n < NN)
            *reinterpret_cast<float4*>(&g_feat[n * F + 4 * c4]) =
                *reinterpret_cast<const float4*>(&Cs[row * CLD + 4 * c4]);
    }
}

// ---------------- exact fp32 scores: el/er = h @ wl/wr + elmax -------------
__global__ __launch_bounds__(256) void scores_kernel(
    const float* __restrict__ hin, int slot)
{
    __shared__ float hsT[F * SPAD];
    __shared__ unsigned shm[4];
    const int tid = threadIdx.x;
    const int base = blockIdx.x * 64;
    if (tid < 4) shm[tid] = fenc(-3.0e38f);

    {
        const int k4 = tid & 31, r0 = tid >> 5;
        #pragma unroll
        for (int j = 0; j < 8; j++) {
            int r = r0 + 8 * j;
            int n = base + r;
            float4 v = (n < NN)
                ? __ldg(reinterpret_cast<const float4*>(&hin[n * F + 4 * k4]))
                : make_float4(0.f, 0.f, 0.f, 0.f);
            hsT[(4 * k4 + 0) * SPAD + r] = v.x;
            hsT[(4 * k4 + 1) * SPAD + r] = v.y;
            hsT[(4 * k4 + 2) * SPAD + r] = v.z;
            hsT[(4 * k4 + 3) * SPAD + r] = v.w;
        }
    }
    __syncthreads();

    const int r  = tid & 63;
    const int hd = tid >> 6;
    const int n  = base + r;
    float el = 0.f, er = 0.f;
    const float4* wl4 = reinterpret_cast<const float4*>(g_wl);
    const float4* wr4 = reinterpret_cast<const float4*>(g_wr);
    #pragma unroll 8
    for (int k4 = 0; k4 < 32; k4++) {
        float4 wlv = __ldg(&wl4[hd * 32 + k4]);
        float4 wrv = __ldg(&wr4[hd * 32 + k4]);
        float h0 = hsT[(4 * k4 + 0) * SPAD + r];
        float h1 = hsT[(4 * k4 + 1) * SPAD + r];
        float h2 = hsT[(4 * k4 + 2) * SPAD + r];
        float h3 = hsT[(4 * k4 + 3) * SPAD + r];
        el = fmaf(h0, wlv.x, fmaf(h1, wlv.y, fmaf(h2, wlv.z, fmaf(h3, wlv.w, el))));
        er = fmaf(h0, wrv.x, fmaf(h1, wrv.y, fmaf(h2, wrv.z, fmaf(h3, wrv.w, er))));
    }
    if (n < NN) {
        g_el[n * 4 + hd] = el;
        g_er[n * 4 + hd] = er;
        atomicMax(&shm[hd], fenc(el));
    }
    __syncthreads();
    if (tid < 4) atomicMax(&g_elmax_u[slot][tid], shm[tid]);
}

// ---------------- per-(edge,head) softmax weights --------------------------
// w[e][h] = exp(leaky(el[src]+er[dst]) - m[dst][h]); m = leaky(elmax+er[dst])
// is a per-node upper bound -> valid softmax shift. One thread per item,
// 4 consecutive threads share an edge (coalesced 16B el/er chunks).
__global__ __launch_bounds__(256) void edgew_kernel(
    const int* __restrict__ src, const int* __restrict__ dst, int slot)
{
    int idx = blockIdx.x * 256 + threadIdx.x;
    if (idx >= NE * 4) return;
    int e = idx >> 2, h = idx & 3;
    int s = __ldg(&src[e]);
    int d = __ldg(&dst[e]);
    float ern = __ldg(&g_er[d * 4 + h]);
    float m = fdec(g_elmax_u[slot][h]) + ern;
    m = (m > 0.f) ? m : 0.2f * m;
    float ee = __ldg(&g_el[s * 4 + h]) + ern;
    ee = (ee > 0.f) ? ee : 0.2f * ee;
    g_ew[idx] = __expf(ee - m);
}

// ---------------- slim aggregation: sum(w * feat[src]) / sum(w) ------------
// One warp per dst node; lane owns 4 features (float4). Per edge: shfl +
// broadcast w-load + float4 gather + 4 FFMA. All score math precomputed.
__global__ __launch_bounds__(256) void gat_agg_kernel(
    const int* __restrict__ src,
    const float* __restrict__ hres,
    float* __restrict__ out,
    int do_act, int do_mean)
{
    const int gw = (blockIdx.x * blockDim.x + threadIdx.x) >> 5;
    if (gw >= NN) return;
    const int lane = threadIdx.x & 31;
    const int n = gw;
    const int e0 = g_rowptr[n];
    const int e1 = g_rowptr[n + 1];
    const int head = lane >> 3;

    float ssum = 0.f;
    float4 acc = make_float4(0.f, 0.f, 0.f, 0.f);
    const float4* feat4 = reinterpret_cast<const float4*>(g_feat);

    for (int basee = e0; basee < e1; basee += 32) {
        int idx = basee + lane;
        int sw = (idx < e1) ? __ldg(&src[idx]) : 0;
        int lim = e1 - basee;
        if (lim > 32) lim = 32;
        for (int c = 0; c < lim; c += 8) {
            #pragma unroll
            for (int j = 0; j < 8; j++) {
                int jj = c + j;
                int s = __shfl_sync(0xffffffffu, sw, jj);
                float wgt = __ldg(&g_ew[(basee + jj) * 4 + head]);  // padded array
                wgt = (jj < lim) ? wgt : 0.f;
                ssum += wgt;
                float4 f = __ldg(&feat4[s * 32 + lane]);
                acc.x = fmaf(wgt, f.x, acc.x);
                acc.y = fmaf(wgt, f.y, acc.y);
                acc.z = fmaf(wgt, f.z, acc.z);
                acc.w = fmaf(wgt, f.w, acc.w);
            }
        }
    }

    float inv = (e1 > e0) ? (1.f / ssum) : 0.f;
    float4 o = make_float4(acc.x * inv, acc.y * inv, acc.z * inv, acc.w * inv);

    if (hres) {
        float4 rr = __ldg(&reinterpret_cast<const float4*>(hres)[n * 32 + lane]);
        o.x += rr.x; o.y += rr.y; o.z += rr.z; o.w += rr.w;
    }
    if (do_act) {  // ELU(alpha=1)
        o.x = (o.x > 0.f) ? o.x : expm1f(o.x);
        o.y = (o.y > 0.f) ? o.y : expm1f(o.y);
        o.z = (o.z > 0.f) ? o.z : expm1f(o.z);
        o.w = (o.w > 0.f) ? o.w : expm1f(o.w);
    }

    if (do_mean) {
        o.x += __shfl_xor_sync(0xffffffffu, o.x, 8);
        o.y += __shfl_xor_sync(0xffffffffu, o.y, 8);
        o.z += __shfl_xor_sync(0xffffffffu, o.z, 8);
        o.w += __shfl_xor_sync(0xffffffffu, o.w, 8);
        o.x += __shfl_xor_sync(0xffffffffu, o.x, 16);
        o.y += __shfl_xor_sync(0xffffffffu, o.y, 16);
        o.z += __shfl_xor_sync(0xffffffffu, o.z, 16);
        o.w += __shfl_xor_sync(0xffffffffu, o.w, 16);
        if (lane < 8) {
            reinterpret_cast<float4*>(out)[n * 8 + lane] =
                make_float4(o.x * 0.25f, o.y * 0.25f, o.z * 0.25f, o.w * 0.25f);
        }
    } else {
        reinterpret_cast<float4*>(out)[n * 32 + lane] = o;
    }
}

// ---------------- launcher --------------------------------------------------
extern "C" void kernel_launch(void* const* d_in, const int* in_sizes, int n_in,
                              void* d_out, int out_size)
{
    const float* x   = (const float*)d_in[0];
    const int*   src = (const int*)d_in[1];
    const int*   dst = (const int*)d_in[2];
    const float* W0  = (const float*)d_in[3];
    const float* al0 = (const float*)d_in[4];
    const float* ar0 = (const float*)d_in[5];
    const float* W1  = (const float*)d_in[6];
    const float* al1 = (const float*)d_in[7];
    const float* ar1 = (const float*)d_in[8];
    const float* W2  = (const float*)d_in[9];
    const float* al2 = (const float*)d_in[10];
    const float* ar2 = (const float*)d_in[11];
    float* out = (float*)d_out;

    float *h1 = nullptr, *h2 = nullptr;
    cudaGetSymbolAddress((void**)&h1, g_h1);
    cudaGetSymbolAddress((void**)&h2, g_h2);

    const int mma_smem = 2 * MT * HLD * (int)sizeof(__half);  // 69632 B
    static int smem_set = 0;
    if (!smem_set) {
        cudaFuncSetAttribute(mma_kernel,
                             cudaFuncAttributeMaxDynamicSharedMemorySize, mma_smem);
        smem_set = 1;
    }

    const int mma_grid    = (NN + MT - 1) / MT;       // 391
    const int scores_grid = (NN + 63) / 64;           // 782
    const int edgew_grid  = (NE * 4 + 255) / 256;     // 12500
    const int agg_grid    = (NN * 32) / 256;          // 6250

    rowptr_kernel<<<(NN + 1 + 255) / 256, 256>>>(dst);

    // layer 0
    mma_kernel<<<mma_grid, 256, mma_smem>>>(x, W0, al0, ar0);
    scores_kernel<<<scores_grid, 256>>>(x, 0);
    edgew_kernel<<<edgew_grid, 256>>>(src, dst, 0);
    gat_agg_kernel<<<agg_grid, 256>>>(src, nullptr, h1, 1, 0);

    // layer 1 (residual h1)
    mma_kernel<<<mma_grid, 256, mma_smem>>>(h1, W1, al1, ar1);
    scores_kernel<<<scores_grid, 256>>>(h1, 1);
    edgew_kernel<<<edgew_grid, 256>>>(src, dst, 1);
    gat_agg_kernel<<<agg_grid, 256>>>(src, h1, h2, 1, 0);

    // layer 2 (residual h2, mean over heads)
    mma_kernel<<<mma_grid, 256, mma_smem>>>(h2, W2, al2, ar2);
    scores_kernel<<<scores_grid, 256>>>(h2, 2);
    edgew_kernel<<<edgew_grid, 256>>>(src, dst, 2);
    gat_agg_kernel<<<agg_grid, 256>>>(src, h2, out, 0, 1);
}

// round 12
// speedup vs baseline: 1.1144x; 1.1144x over previous
#include <cuda_runtime.h>
#include <cuda_fp16.h>
#include <mma.h>
#include <math.h>
#include <stdint.h>

using namespace nvcuda;

#define NN 50000
#define NE 800000
#define F  128
#define MT 128        // rows per MMA block
#define HLD 136       // half leading dim for A/B smem
#define CLD 132       // float leading dim for C staging
#define SPAD 65       // scores transposed-tile pad

// ---------------- scratch (device globals; no allocation allowed) ----------
__device__ __align__(16) float g_feat[NN * F];
__device__ __align__(16) float g_h1[NN * F];
__device__ __align__(16) float g_h2[NN * F];
__device__ __align__(16) float g_el[NN * 4];
__device__ __align__(16) float g_er[NN * 4];
__device__ __align__(16) float g_wl[4 * F];   // W @ al[h]
__device__ __align__(16) float g_wr[4 * F];   // W @ ar[h]
__device__ int g_rowptr[NN + 1];

// ---------------- row_ptr from sorted dst via lower_bound ------------------
__global__ void rowptr_kernel(const int* __restrict__ dst) {
    int n = blockIdx.x * blockDim.x + threadIdx.x;
    if (n > NN) return;
    int lo = 0, hi = NE;
    while (lo < hi) {
        int mid = (lo + hi) >> 1;
        if (dst[mid] < n) lo = mid + 1; else hi = mid;
    }
    g_rowptr[n] = lo;
}

// ---------------- fp16 WMMA GEMM: feat = h @ W  (+ wl/wr on block 0) -------
extern __shared__ __align__(16) char s_raw[];

__global__ __launch_bounds__(256) void mma_kernel(
    const float* __restrict__ hin, const float* __restrict__ W,
    const float* __restrict__ al, const float* __restrict__ ar)
{
    __half* As = reinterpret_cast<__half*>(s_raw);               // [128][HLD]
    __half* Bs = reinterpret_cast<__half*>(s_raw) + MT * HLD;    // [128][HLD]
    float*  Cs = reinterpret_cast<float*>(s_raw);                // [128][CLD]
    const int tid  = threadIdx.x;
    const int base = blockIdx.x * MT;

    // block 0: wl[h]=W@al[h], wr[h]=W@ar[h] (exact fp32)
    if (blockIdx.x == 0) {
        #pragma unroll
        for (int j = 0; j < 4; j++) {
            int o = tid + 256 * j;
            int k = o & 127, hh = o >> 7, h = hh & 3;
            const float* vec = (hh < 4) ? al : ar;
            float s = 0.f;
            #pragma unroll
            for (int d = 0; d < 32; d++)
                s = fmaf(__ldg(&W[k * F + h * 32 + d]), __ldg(&vec[h * 32 + d]), s);
            if (hh < 4) g_wl[h * F + k] = s; else g_wr[h * F + k] = s;
        }
    }

    // ---- fill A (h tile, fp16) and B (W, fp16), coalesced ----
    #pragma unroll
    for (int i = 0; i < 16; i++) {
        int idx = tid + 256 * i;
        int row = idx >> 5, c4 = idx & 31;
        int n = base + row;
        float4 v = (n < NN)
            ? __ldg(reinterpret_cast<const float4*>(&hin[n * F + 4 * c4]))
            : make_float4(0.f, 0.f, 0.f, 0.f);
        __half2 a01 = __floats2half2_rn(v.x, v.y);
        __half2 a23 = __floats2half2_rn(v.z, v.w);
        uint2 pa;
        pa.x = *reinterpret_cast<unsigned*>(&a01);
        pa.y = *reinterpret_cast<unsigned*>(&a23);
        *reinterpret_cast<uint2*>(&As[row * HLD + 4 * c4]) = pa;

        float4 wv = __ldg(reinterpret_cast<const float4*>(&W[idx * 4]));
        __half2 b01 = __floats2half2_rn(wv.x, wv.y);
        __half2 b23 = __floats2half2_rn(wv.z, wv.w);
        uint2 pb;
        pb.x = *reinterpret_cast<unsigned*>(&b01);
        pb.y = *reinterpret_cast<unsigned*>(&b23);
        *reinterpret_cast<uint2*>(&Bs[row * HLD + 4 * c4]) = pb;
    }
    __syncthreads();

    const int w  = tid >> 5;
    const int wr = w & 3;       // rows 32*wr .. +31
    const int wc = w >> 2;      // cols 64*wc .. +63

    wmma::fragment<wmma::accumulator, 16, 16, 16, float> c[2][4];
    #pragma unroll
    for (int i = 0; i < 2; i++)
        #pragma unroll
        for (int j = 0; j < 4; j++) wmma::fill_fragment(c[i][j], 0.f);

    #pragma unroll
    for (int k = 0; k < 8; k++) {
        wmma::fragment<wmma::matrix_a, 16, 16, 16, __half, wmma::row_major> a[2];
        wmma::fragment<wmma::matrix_b, 16, 16, 16, __half, wmma::row_major> b[4];
        #pragma unroll
        for (int i = 0; i < 2; i++)
            wmma::load_matrix_sync(a[i], &As[(32 * wr + 16 * i) * HLD + 16 * k], HLD);
        #pragma unroll
        for (int j = 0; j < 4; j++)
            wmma::load_matrix_sync(b[j], &Bs[16 * k * HLD + 64 * wc + 16 * j], HLD);
        #pragma unroll
        for (int i = 0; i < 2; i++)
            #pragma unroll
            for (int j = 0; j < 4; j++)
                wmma::mma_sync(c[i][j], a[i], b[j], c[i][j]);
    }
    __syncthreads();

    #pragma unroll
    for (int i = 0; i < 2; i++)
        #pragma unroll
        for (int j = 0; j < 4; j++)
            wmma::store_matrix_sync(
                &Cs[(32 * wr + 16 * i) * CLD + 64 * wc + 16 * j],
                c[i][j], CLD, wmma::mem_row_major);
    __syncthreads();

    // ---- coalesced fp32 feat writeout ----
    #pragma unroll
    for (int i = 0; i < 16; i++) {
        int idx = tid + 256 * i;
        int row = idx >> 5, c4 = idx & 31;
        int n = base + row;
        if (n < NN)
            *reinterpret_cast<float4*>(&g_feat[n * F + 4 * c4]) =
                *reinterpret_cast<const float4*>(&Cs[row * CLD + 4 * c4]);
    }
}

// ---------------- exact fp32 scores: el/er = h @ wl/wr ---------------------
__global__ __launch_bounds__(256) void scores_kernel(const float* __restrict__ hin)
{
    __shared__ float hsT[F * SPAD];
    const int tid = threadIdx.x;
    const int base = blockIdx.x * 64;

    {
        const int k4 = tid & 31, r0 = tid >> 5;
        #pragma unroll
        for (int j = 0; j < 8; j++) {
            int r = r0 + 8 * j;
            int n = base + r;
            float4 v = (n < NN)
                ? __ldg(reinterpret_cast<const float4*>(&hin[n * F + 4 * k4]))
                : make_float4(0.f, 0.f, 0.f, 0.f);
            hsT[(4 * k4 + 0) * SPAD + r] = v.x;
            hsT[(4 * k4 + 1) * SPAD + r] = v.y;
            hsT[(4 * k4 + 2) * SPAD + r] = v.z;
            hsT[(4 * k4 + 3) * SPAD + r] = v.w;
        }
    }
    __syncthreads();

    const int r  = tid & 63;
    const int hd = tid >> 6;
    const int n  = base + r;
    float el = 0.f, er = 0.f;
    const float4* wl4 = reinterpret_cast<const float4*>(g_wl);
    const float4* wr4 = reinterpret_cast<const float4*>(g_wr);
    #pragma unroll 8
    for (int k4 = 0; k4 < 32; k4++) {
        float4 wlv = __ldg(&wl4[hd * 32 + k4]);
        float4 wrv = __ldg(&wr4[hd * 32 + k4]);
        float h0 = hsT[(4 * k4 + 0) * SPAD + r];
        float h1 = hsT[(4 * k4 + 1) * SPAD + r];
        float h2 = hsT[(4 * k4 + 2) * SPAD + r];
        float h3 = hsT[(4 * k4 + 3) * SPAD + r];
        el = fmaf(h0, wlv.x, fmaf(h1, wlv.y, fmaf(h2, wlv.z, fmaf(h3, wlv.w, el))));
        er = fmaf(h0, wrv.x, fmaf(h1, wrv.y, fmaf(h2, wrv.z, fmaf(h3, wrv.w, er))));
    }
    if (n < NN) {
        g_el[n * 4 + hd] = el;
        g_er[n * 4 + hd] = er;
    }
}

// ---------------- fused softmax + aggregation, cooperative weights ---------
// One warp per dst node. No shift (softmax is shift-invariant; |scores| small
// => exp safe in fp32). Per 32-edge window: lane (g=lane>>3, p=lane&7)
// computes the weight of edge base+8k+p for head g (k=0..3) -> score math
// runs 4x/window instead of 32x. j-loop: shfl(s)+shfl(w)+LDG feat+4 FFMA.
__global__ __launch_bounds__(256) void gat_agg_kernel(
    const int* __restrict__ src,
    const float* __restrict__ hres,
    float* __restrict__ out,
    int do_act, int do_mean)
{
    const int gw = (blockIdx.x * blockDim.x + threadIdx.x) >> 5;
    if (gw >= NN) return;
    const int lane = threadIdx.x & 31;
    const int n = gw;
    const int e0 = g_rowptr[n];
    const int e1 = g_rowptr[n + 1];
    const int g = lane >> 3;          // head owned by this lane
    const int p = lane & 7;
    const int shfl_base = lane & 24;  // first lane of my head group
    const float ern = g_er[n * 4 + g];

    float ssum = 0.f;
    float4 acc = make_float4(0.f, 0.f, 0.f, 0.f);
    const float4* feat4 = reinterpret_cast<const float4*>(g_feat);

    for (int basee = e0; basee < e1; basee += 32) {
        int idx = basee + lane;
        int sw = (idx < e1) ? __ldg(&src[idx]) : 0;   // pad -> node 0 (valid)

        // cooperative weights: wv[k] = weight of edge basee+8k+p at head g
        float wv[4];
        #pragma unroll
        for (int k = 0; k < 4; k++) {
            int jj = 8 * k + p;
            int s = __shfl_sync(0xffffffffu, sw, jj);
            float e = __ldg(&g_el[s * 4 + g]) + ern;
            e = (e > 0.f) ? e : 0.2f * e;              // leaky_relu(0.2)
            float wgt = __expf(e);
            wgt = (basee + jj < e1) ? wgt : 0.f;
            wv[k] = wgt;
            ssum += wgt;
        }

        // gather-accumulate (bounds warp-uniform -> shfl-safe)
        #pragma unroll
        for (int k = 0; k < 4; k++) {
            if (basee + 8 * k >= e1) break;
            #pragma unroll
            for (int p2 = 0; p2 < 8; p2++) {
                int jj = 8 * k + p2;
                int s = __shfl_sync(0xffffffffu, sw, jj);
                float wgt = __shfl_sync(0xffffffffu, wv[k], shfl_base + p2);
                float4 f = __ldg(&feat4[s * 32 + lane]);
                acc.x = fmaf(wgt, f.x, acc.x);
                acc.y = fmaf(wgt, f.y, acc.y);
                acc.z = fmaf(wgt, f.z, acc.z);
                acc.w = fmaf(wgt, f.w, acc.w);
            }
        }
    }

    // group-reduce ssum across the 8 lanes of this head
    ssum += __shfl_xor_sync(0xffffffffu, ssum, 1);
    ssum += __shfl_xor_sync(0xffffffffu, ssum, 2);
    ssum += __shfl_xor_sync(0xffffffffu, ssum, 4);

    float inv = (e1 > e0) ? (1.f / ssum) : 0.f;
    float4 o = make_float4(acc.x * inv, acc.y * inv, acc.z * inv, acc.w * inv);

    if (hres) {
        float4 rr = __ldg(&reinterpret_cast<const float4*>(hres)[n * 32 + lane]);
        o.x += rr.x; o.y += rr.y; o.z += rr.z; o.w += rr.w;
    }
    if (do_act) {  // ELU(alpha=1)
        o.x = (o.x > 0.f) ? o.x : expm1f(o.x);
        o.y = (o.y > 0.f) ? o.y : expm1f(o.y);
        o.z = (o.z > 0.f) ? o.z : expm1f(o.z);
        o.w = (o.w > 0.f) ? o.w : expm1f(o.w);
    }

    if (do_mean) {
        o.x += __shfl_xor_sync(0xffffffffu, o.x, 8);
        o.y += __shfl_xor_sync(0xffffffffu, o.y, 8);
        o.z += __shfl_xor_sync(0xffffffffu, o.z, 8);
        o.w += __shfl_xor_sync(0xffffffffu, o.w, 8);
        o.x += __shfl_xor_sync(0xffffffffu, o.x, 16);
        o.y += __shfl_xor_sync(0xffffffffu, o.y, 16);
        o.z += __shfl_xor_sync(0xffffffffu, o.z, 16);
        o.w += __shfl_xor_sync(0xffffffffu, o.w, 16);
        if (lane < 8) {
            reinterpret_cast<float4*>(out)[n * 8 + lane] =
                make_float4(o.x * 0.25f, o.y * 0.25f, o.z * 0.25f, o.w * 0.25f);
        }
    } else {
        reinterpret_cast<float4*>(out)[n * 32 + lane] = o;
    }
}

// ---------------- launcher --------------------------------------------------
extern "C" void kernel_launch(void* const* d_in, const int* in_sizes, int n_in,
                              void* d_out, int out_size)
{
    const float* x   = (const float*)d_in[0];
    const int*   src = (const int*)d_in[1];
    const int*   dst = (const int*)d_in[2];
    const float* W0  = (const float*)d_in[3];
    const float* al0 = (const float*)d_in[4];
    const float* ar0 = (const float*)d_in[5];
    const float* W1  = (const float*)d_in[6];
    const float* al1 = (const float*)d_in[7];
    const float* ar1 = (const float*)d_in[8];
    const float* W2  = (const float*)d_in[9];
    const float* al2 = (const float*)d_in[10];
    const float* ar2 = (const float*)d_in[11];
    float* out = (float*)d_out;

    float *h1 = nullptr, *h2 = nullptr;
    cudaGetSymbolAddress((void**)&h1, g_h1);
    cudaGetSymbolAddress((void**)&h2, g_h2);

    const int mma_smem = 2 * MT * HLD * (int)sizeof(__half);  // 69632 B
    static int smem_set = 0;
    if (!smem_set) {
        cudaFuncSetAttribute(mma_kernel,
                             cudaFuncAttributeMaxDynamicSharedMemorySize, mma_smem);
        smem_set = 1;
    }

    const int mma_grid    = (NN + MT - 1) / MT;   // 391
    const int scores_grid = (NN + 63) / 64;       // 782
    const int agg_grid    = (NN * 32) / 256;      // 6250

    rowptr_kernel<<<(NN + 1 + 255) / 256, 256>>>(dst);

    // layer 0
    mma_kernel<<<mma_grid, 256, mma_smem>>>(x, W0, al0, ar0);
    scores_kernel<<<scores_grid, 256>>>(x);
    gat_agg_kernel<<<agg_grid, 256>>>(src, nullptr, h1, 1, 0);

    // layer 1 (residual h1)
    mma_kernel<<<mma_grid, 256, mma_smem>>>(h1, W1, al1, ar1);
    scores_kernel<<<scores_grid, 256>>>(h1);
    gat_agg_kernel<<<agg_grid, 256>>>(src, h1, h2, 1, 0);

    // layer 2 (residual h2, mean over heads)
    mma_kernel<<<mma_grid, 256, mma_smem>>>(h2, W2, al2, ar2);
    scores_kernel<<<scores_grid, 256>>>(h2);
    gat_agg_kernel<<<agg_grid, 256>>>(src, h2, out, 0, 1);
}

// round 13
// speedup vs baseline: 1.1508x; 1.0326x over previous
#include <cuda_runtime.h>
#include <cuda_fp16.h>
#include <mma.h>
#include <math.h>
#include <stdint.h>

using namespace nvcuda;

#define NN 50000
#define NE 800000
#define F  128
#define MT 128        // rows per MMA block
#define HLD 136       // half leading dim for A/B smem
#define CLD 132       // float leading dim for C staging
#define SPAD 65       // scores transposed-tile pad
#define MMA_GRID   391
#define SCORES_GRID 782
#define AGG_GRID   6250

// ---------------- scratch (device globals; no allocation allowed) ----------
__device__ __align__(16) __half g_feath[NN * F];
__device__ __align__(16) float g_h1[NN * F];
__device__ __align__(16) float g_h2[NN * F];
__device__ __align__(16) float g_el[NN * 4];
__device__ __align__(16) float g_er[NN * 4];
__device__ __align__(16) float g_wl[3][4 * F];   // W @ al[h], per layer
__device__ __align__(16) float g_wr[3][4 * F];   // W @ ar[h]
__device__ int g_rowptr[NN + 1];

// ---------------- wprep: wl[h]=W@al[h], wr[h]=W@ar[h] (exact fp32) ---------
__device__ __forceinline__ void wprep_dev(
    const float* __restrict__ W, const float* __restrict__ al,
    const float* __restrict__ ar, int slot)
{
    const int tid = threadIdx.x;
    #pragma unroll
    for (int j = 0; j < 4; j++) {
        int o = tid + 256 * j;                 // 1024 outputs
        int k = o & 127, hh = o >> 7, h = hh & 3;
        const float* vec = (hh < 4) ? al : ar;
        float s = 0.f;
        #pragma unroll
        for (int d = 0; d < 32; d++)
            s = fmaf(__ldg(&W[k * F + h * 32 + d]), __ldg(&vec[h * 32 + d]), s);
        if (hh < 4) g_wl[slot][h * F + k] = s; else g_wr[slot][h * F + k] = s;
    }
}

// ---------------- row_ptr (sorted dst) + layer-0 wprep ---------------------
__global__ void rowptr_kernel(const int* __restrict__ dst,
                              const float* __restrict__ W0,
                              const float* __restrict__ al0,
                              const float* __restrict__ ar0)
{
    if (blockIdx.x == gridDim.x - 1) { wprep_dev(W0, al0, ar0, 0); return; }
    int n = blockIdx.x * blockDim.x + threadIdx.x;
    if (n > NN) return;
    int lo = 0, hi = NE;
    while (lo < hi) {
        int mid = (lo + hi) >> 1;
        if (dst[mid] < n) lo = mid + 1; else hi = mid;
    }
    g_rowptr[n] = lo;
}

// ---------------- fused MMA (fp16 WMMA) + scores (exact fp32) --------------
// Blocks [0, MMA_GRID): 128x128 feat tile, fp16 writeout.
// Blocks [MMA_GRID, MMA_GRID+SCORES_GRID): 64 rows of el/er from wl/wr.
extern __shared__ __align__(16) char s_raw[];

__global__ __launch_bounds__(256) void mma_scores_kernel(
    const float* __restrict__ hin, const float* __restrict__ W, int slot)
{
    const int tid = threadIdx.x;

    if (blockIdx.x >= MMA_GRID) {
        // ================= scores path =================
        float* hsT = reinterpret_cast<float*>(s_raw);   // [F][SPAD]
        const int base = (blockIdx.x - MMA_GRID) * 64;
        {
            const int k4 = tid & 31, r0 = tid >> 5;
            #pragma unroll
            for (int j = 0; j < 8; j++) {
                int r = r0 + 8 * j;
                int n = base + r;
                float4 v = (n < NN)
                    ? __ldg(reinterpret_cast<const float4*>(&hin[n * F + 4 * k4]))
                    : make_float4(0.f, 0.f, 0.f, 0.f);
                hsT[(4 * k4 + 0) * SPAD + r] = v.x;
                hsT[(4 * k4 + 1) * SPAD + r] = v.y;
                hsT[(4 * k4 + 2) * SPAD + r] = v.z;
                hsT[(4 * k4 + 3) * SPAD + r] = v.w;
            }
        }
        __syncthreads();

        const int r  = tid & 63;
        const int hd = tid >> 6;
        const int n  = base + r;
        float el = 0.f, er = 0.f;
        const float4* wl4 = reinterpret_cast<const float4*>(g_wl[slot]);
        const float4* wr4 = reinterpret_cast<const float4*>(g_wr[slot]);
        #pragma unroll 8
        for (int k4 = 0; k4 < 32; k4++) {
            float4 wlv = __ldg(&wl4[hd * 32 + k4]);
            float4 wrv = __ldg(&wr4[hd * 32 + k4]);
            float h0 = hsT[(4 * k4 + 0) * SPAD + r];
            float h1 = hsT[(4 * k4 + 1) * SPAD + r];
            float h2 = hsT[(4 * k4 + 2) * SPAD + r];
            float h3 = hsT[(4 * k4 + 3) * SPAD + r];
            el = fmaf(h0, wlv.x, fmaf(h1, wlv.y, fmaf(h2, wlv.z, fmaf(h3, wlv.w, el))));
            er = fmaf(h0, wrv.x, fmaf(h1, wrv.y, fmaf(h2, wrv.z, fmaf(h3, wrv.w, er))));
        }
        if (n < NN) {
            g_el[n * 4 + hd] = el;
            g_er[n * 4 + hd] = er;
        }
        return;
    }

    // ================= MMA path =================
    __half* As = reinterpret_cast<__half*>(s_raw);               // [128][HLD]
    __half* Bs = reinterpret_cast<__half*>(s_raw) + MT * HLD;    // [128][HLD]
    float*  Cs = reinterpret_cast<float*>(s_raw);                // [128][CLD]
    const int base = blockIdx.x * MT;

    #pragma unroll
    for (int i = 0; i < 16; i++) {
        int idx = tid + 256 * i;
        int row = idx >> 5, c4 = idx & 31;
        int n = base + row;
        float4 v = (n < NN)
            ? __ldg(reinterpret_cast<const float4*>(&hin[n * F + 4 * c4]))
            : make_float4(0.f, 0.f, 0.f, 0.f);
        __half2 a01 = __floats2half2_rn(v.x, v.y);
        __half2 a23 = __floats2half2_rn(v.z, v.w);
        uint2 pa;
        pa.x = *reinterpret_cast<unsigned*>(&a01);
        pa.y = *reinterpret_cast<unsigned*>(&a23);
        *reinterpret_cast<uint2*>(&As[row * HLD + 4 * c4]) = pa;

        float4 wv = __ldg(reinterpret_cast<const float4*>(&W[idx * 4]));
        __half2 b01 = __floats2half2_rn(wv.x, wv.y);
        __half2 b23 = __floats2half2_rn(wv.z, wv.w);
        uint2 pb;
        pb.x = *reinterpret_cast<unsigned*>(&b01);
        pb.y = *reinterpret_cast<unsigned*>(&b23);
        *reinterpret_cast<uint2*>(&Bs[row * HLD + 4 * c4]) = pb;
    }
    __syncthreads();

    const int w  = tid >> 5;
    const int wr = w & 3;       // rows 32*wr .. +31
    const int wc = w >> 2;      // cols 64*wc .. +63

    wmma::fragment<wmma::accumulator, 16, 16, 16, float> c[2][4];
    #pragma unroll
    for (int i = 0; i < 2; i++)
        #pragma unroll
        for (int j = 0; j < 4; j++) wmma::fill_fragment(c[i][j], 0.f);

    #pragma unroll
    for (int k = 0; k < 8; k++) {
        wmma::fragment<wmma::matrix_a, 16, 16, 16, __half, wmma::row_major> a[2];
        wmma::fragment<wmma::matrix_b, 16, 16, 16, __half, wmma::row_major> b[4];
        #pragma unroll
        for (int i = 0; i < 2; i++)
            wmma::load_matrix_sync(a[i], &As[(32 * wr + 16 * i) * HLD + 16 * k], HLD);
        #pragma unroll
        for (int j = 0; j < 4; j++)
            wmma::load_matrix_sync(b[j], &Bs[16 * k * HLD + 64 * wc + 16 * j], HLD);
        #pragma unroll
        for (int i = 0; i < 2; i++)
            #pragma unroll
            for (int j = 0; j < 4; j++)
                wmma::mma_sync(c[i][j], a[i], b[j], c[i][j]);
    }
    __syncthreads();

    #pragma unroll
    for (int i = 0; i < 2; i++)
        #pragma unroll
        for (int j = 0; j < 4; j++)
            wmma::store_matrix_sync(
                &Cs[(32 * wr + 16 * i) * CLD + 64 * wc + 16 * j],
                c[i][j], CLD, wmma::mem_row_major);
    __syncthreads();

    // ---- coalesced fp16 feat writeout ----
    #pragma unroll
    for (int i = 0; i < 16; i++) {
        int idx = tid + 256 * i;
        int row = idx >> 5, c4 = idx & 31;
        int n = base + row;
        if (n < NN) {
            float4 v = *reinterpret_cast<const float4*>(&Cs[row * CLD + 4 * c4]);
            __half2 p01 = __floats2half2_rn(v.x, v.y);
            __half2 p23 = __floats2half2_rn(v.z, v.w);
            uint2 pk;
            pk.x = *reinterpret_cast<unsigned*>(&p01);
            pk.y = *reinterpret_cast<unsigned*>(&p23);
            *reinterpret_cast<uint2*>(&g_feath[n * F + 4 * c4]) = pk;
        }
    }
}

// ---------------- fused softmax + aggregation (+ next-layer wprep) ---------
// One warp per dst node, cooperative weights (4x/window score math), fp16
// gather (256B/edge). No softmax shift (shift-invariant; |scores| small).
__global__ __launch_bounds__(256) void gat_agg_kernel(
    const int* __restrict__ src,
    const float* __restrict__ hres,
    float* __restrict__ out,
    int slot, int do_act, int do_mean,
    const float* __restrict__ Wn, const float* __restrict__ aln,
    const float* __restrict__ arn)
{
    if (blockIdx.x == AGG_GRID) {            // tail block: next layer's wprep
        if (Wn) wprep_dev(Wn, aln, arn, slot + 1);
        return;
    }
    const int gw = (blockIdx.x * blockDim.x + threadIdx.x) >> 5;
    if (gw >= NN) return;
    const int lane = threadIdx.x & 31;
    const int n = gw;
    const int e0 = g_rowptr[n];
    const int e1 = g_rowptr[n + 1];
    const int g = lane >> 3;          // head owned by this lane
    const int p = lane & 7;
    const int shfl_base = lane & 24;
    const float ern = g_er[n * 4 + g];

    float ssum = 0.f;
    float4 acc = make_float4(0.f, 0.f, 0.f, 0.f);
    const uint2* feat8 = reinterpret_cast<const uint2*>(g_feath);

    for (int basee = e0; basee < e1; basee += 32) {
        int idx = basee + lane;
        int sw = (idx < e1) ? __ldg(&src[idx]) : 0;

        // cooperative weights: wv[k] = weight of edge basee+8k+p at head g
        float wv[4];
        #pragma unroll
        for (int k = 0; k < 4; k++) {
            int jj = 8 * k + p;
            int s = __shfl_sync(0xffffffffu, sw, jj);
            float e = __ldg(&g_el[s * 4 + g]) + ern;
            e = (e > 0.f) ? e : 0.2f * e;              // leaky_relu(0.2)
            float wgt = __expf(e);
            wgt = (basee + jj < e1) ? wgt : 0.f;
            wv[k] = wgt;
            ssum += wgt;
        }

        // gather-accumulate (bounds warp-uniform -> shfl-safe)
        #pragma unroll
        for (int k = 0; k < 4; k++) {
            if (basee + 8 * k >= e1) break;
            #pragma unroll
            for (int p2 = 0; p2 < 8; p2++) {
                int jj = 8 * k + p2;
                int s = __shfl_sync(0xffffffffu, sw, jj);
                float wgt = __shfl_sync(0xffffffffu, wv[k], shfl_base + p2);
                uint2 pk = __ldg(&feat8[s * 32 + lane]);
                float2 f01 = __half22float2(*reinterpret_cast<__half2*>(&pk.x));
                float2 f23 = __half22float2(*reinterpret_cast<__half2*>(&pk.y));
                acc.x = fmaf(wgt, f01.x, acc.x);
                acc.y = fmaf(wgt, f01.y, acc.y);
                acc.z = fmaf(wgt, f23.x, acc.z);
                acc.w = fmaf(wgt, f23.y, acc.w);
            }
        }
    }

    // group-reduce ssum across the 8 lanes of this head
    ssum += __shfl_xor_sync(0xffffffffu, ssum, 1);
    ssum += __shfl_xor_sync(0xffffffffu, ssum, 2);
    ssum += __shfl_xor_sync(0xffffffffu, ssum, 4);

    float inv = (e1 > e0) ? (1.f / ssum) : 0.f;
    float4 o = make_float4(acc.x * inv, acc.y * inv, acc.z * inv, acc.w * inv);

    if (hres) {
        float4 rr = __ldg(&reinterpret_cast<const float4*>(hres)[n * 32 + lane]);
        o.x += rr.x; o.y += rr.y; o.z += rr.z; o.w += rr.w;
    }
    if (do_act) {  // ELU(alpha=1)
        o.x = (o.x > 0.f) ? o.x : expm1f(o.x);
        o.y = (o.y > 0.f) ? o.y : expm1f(o.y);
        o.z = (o.z > 0.f) ? o.z : expm1f(o.z);
        o.w = (o.w > 0.f) ? o.w : expm1f(o.w);
    }

    if (do_mean) {
        o.x += __shfl_xor_sync(0xffffffffu, o.x, 8);
        o.y += __shfl_xor_sync(0xffffffffu, o.y, 8);
        o.z += __shfl_xor_sync(0xffffffffu, o.z, 8);
        o.w += __shfl_xor_sync(0xffffffffu, o.w, 8);
        o.x += __shfl_xor_sync(0xffffffffu, o.x, 16);
        o.y += __shfl_xor_sync(0xffffffffu, o.y, 16);
        o.z += __shfl_xor_sync(0xffffffffu, o.z, 16);
        o.w += __shfl_xor_sync(0xffffffffu, o.w, 16);
        if (lane < 8) {
            reinterpret_cast<float4*>(out)[n * 8 + lane] =
                make_float4(o.x * 0.25f, o.y * 0.25f, o.z * 0.25f, o.w * 0.25f);
        }
    } else {
        reinterpret_cast<float4*>(out)[n * 32 + lane] = o;
    }
}

// ---------------- launcher --------------------------------------------------
extern "C" void kernel_launch(void* const* d_in, const int* in_sizes, int n_in,
                              void* d_out, int out_size)
{
    const float* x   = (const float*)d_in[0];
    const int*   src = (const int*)d_in[1];
    const int*   dst = (const int*)d_in[2];
    const float* W0  = (const float*)d_in[3];
    const float* al0 = (const float*)d_in[4];
    const float* ar0 = (const float*)d_in[5];
    const float* W1  = (const float*)d_in[6];
    const float* al1 = (const float*)d_in[7];
    const float* ar1 = (const float*)d_in[8];
    const float* W2  = (const float*)d_in[9];
    const float* al2 = (const float*)d_in[10];
    const float* ar2 = (const float*)d_in[11];
    float* out = (float*)d_out;

    float *h1 = nullptr, *h2 = nullptr;
    cudaGetSymbolAddress((void**)&h1, g_h1);
    cudaGetSymbolAddress((void**)&h2, g_h2);

    const int mma_smem = 2 * MT * HLD * (int)sizeof(__half);  // 69632 B
    static int smem_set = 0;
    if (!smem_set) {
        cudaFuncSetAttribute(mma_scores_kernel,
                             cudaFuncAttributeMaxDynamicSharedMemorySize, mma_smem);
        smem_set = 1;
    }

    const int ms_grid = MMA_GRID + SCORES_GRID;      // 1173
    const int rp_grid = (NN + 1 + 255) / 256 + 1;    // rowptr + wprep0

    rowptr_kernel<<<rp_grid, 256>>>(dst, W0, al0, ar0);

    // layer 0 (agg tail-block preps layer 1)
    mma_scores_kernel<<<ms_grid, 256, mma_smem>>>(x, W0, 0);
    gat_agg_kernel<<<AGG_GRID + 1, 256>>>(src, nullptr, h1, 0, 1, 0, W1, al1, ar1);

    // layer 1 (agg tail-block preps layer 2)
    mma_scores_kernel<<<ms_grid, 256, mma_smem>>>(h1, W1, 1);
    gat_agg_kernel<<<AGG_GRID + 1, 256>>>(src, h1, h2, 1, 1, 0, W2, al2, ar2);

    // layer 2 (mean over heads)
    mma_scores_kernel<<<ms_grid, 256, mma_smem>>>(h2, W2, 2);
    gat_agg_kernel<<<AGG_GRID + 1, 256>>>(src, h2, out, 2, 0, 1,
                                          nullptr, nullptr, nullptr);
}